// round 2
// baseline (speedup 1.0000x reference)
#include <cuda_runtime.h>
#include <math.h>

#define B_   4096
#define T_   48
#define D_   32
#define H_   256
#define L_   128
#define HID_ 256
#define E_   8
#define NH_  48
#define PI_F 3.14159265358979323846f

// ---------------- scratch (device globals; no allocation allowed) ----------------
__device__ float g_hA[B_ * H_];
__device__ float g_hB[B_ * H_];
__device__ float g_obs[T_ * B_];
__device__ float g_z0out[B_ * 2 * L_];
__device__ float g_z[B_ * L_];
__device__ float g_ztmp[B_ * L_];
__device__ float g_k1[B_ * L_];
__device__ float g_k2[B_ * L_];
__device__ float g_k3[B_ * L_];
__device__ float g_k4[B_ * L_];
__device__ float g_m1[B_ * HID_];
__device__ float g_m2[B_ * HID_];
__device__ float g_ztraj[(size_t)B_ * NH_ * L_];   // [B, NH, L]

__device__ __forceinline__ float sigmoidf_(float x) {
    return 1.0f / (1.0f + expf(-x));
}

// ---------------- obs mask: any_obs[t,b] = (sum_k mask[b,t,k]) > 0 ----------------
__global__ void obs_kernel(const float* __restrict__ mask) {
    int i = blockIdx.x * blockDim.x + threadIdx.x;  // over B_*T_
    if (i >= B_ * T_) return;
    int b = i / T_, t = i % T_;
    const float* mp = mask + (size_t)i * D_;
    float s = 0.f;
#pragma unroll
    for (int k = 0; k < D_; k++) s += mp[k];
    g_obs[t * B_ + b] = (s > 0.f) ? 1.0f : 0.0f;
}

// ---------------- one GRU step (reversed-time scan body) ----------------
// h_out[b,j] computed from inp_t=[X[:,t,:], mask[:,t,:]] (K=64) and h_in (K=256).
// 4 accumulators per output: r-sum, z-sum, i_n (ih only), h_n (hh only).
__global__ __launch_bounds__(256) void gru_step_kernel(
    const float* __restrict__ X, const float* __restrict__ mask,
    const float* __restrict__ w_ih, const float* __restrict__ w_hh,
    const float* __restrict__ b_ih, const float* __restrict__ b_hh,
    const float* __restrict__ h_in, float* __restrict__ h_out, int t)
{
    __shared__ float As[64][33];
    __shared__ float Wr[64][33];
    __shared__ float Wz[64][33];
    __shared__ float Wn[64][33];

    int tid = threadIdx.x;
    int tx = tid & 15, ty = tid >> 4;
    int row0 = blockIdx.x * 64;
    int col0 = blockIdx.y * 64;

    float accR[16], accZ[16], accN1[16], accN2[16];
#pragma unroll
    for (int i = 0; i < 16; i++) { accR[i] = 0.f; accZ[i] = 0.f; accN1[i] = 0.f; accN2[i] = 0.f; }

    // ---- phase 1: input part, K=64 (chunk 0 = X, chunk 1 = mask) ----
    for (int c = 0; c < 2; c++) {
        const float* Ab = (c == 0) ? X : mask;
        int k0 = c * 32;
#pragma unroll
        for (int i = 0; i < 8; i++) {
            int e = tid + i * 256;
            int m = e >> 5, k = e & 31;
            As[m][k] = Ab[((size_t)(row0 + m) * T_ + t) * D_ + k];
        }
#pragma unroll
        for (int i = 0; i < 8; i++) {
            int e = tid + i * 256;
            int n = e >> 5, k = e & 31;
            Wr[n][k] = w_ih[(size_t)(col0 + n) * 64 + k0 + k];
            Wz[n][k] = w_ih[(size_t)(256 + col0 + n) * 64 + k0 + k];
            Wn[n][k] = w_ih[(size_t)(512 + col0 + n) * 64 + k0 + k];
        }
        __syncthreads();
#pragma unroll 4
        for (int k = 0; k < 32; k++) {
            float a[4], wr[4], wz[4], wn[4];
#pragma unroll
            for (int i = 0; i < 4; i++) a[i] = As[ty * 4 + i][k];
#pragma unroll
            for (int j = 0; j < 4; j++) { wr[j] = Wr[tx * 4 + j][k]; wz[j] = Wz[tx * 4 + j][k]; wn[j] = Wn[tx * 4 + j][k]; }
#pragma unroll
            for (int i = 0; i < 4; i++)
#pragma unroll
                for (int j = 0; j < 4; j++) {
                    accR[i * 4 + j]  += a[i] * wr[j];
                    accZ[i * 4 + j]  += a[i] * wz[j];
                    accN1[i * 4 + j] += a[i] * wn[j];
                }
        }
        __syncthreads();
    }

    // ---- phase 2: hidden part, K=256 ----
    for (int c = 0; c < 8; c++) {
        int k0 = c * 32;
#pragma unroll
        for (int i = 0; i < 8; i++) {
            int e = tid + i * 256;
            int m = e >> 5, k = e & 31;
            As[m][k] = h_in[(size_t)(row0 + m) * H_ + k0 + k];
        }
#pragma unroll
        for (int i = 0; i < 8; i++) {
            int e = tid + i * 256;
            int n = e >> 5, k = e & 31;
            Wr[n][k] = w_hh[(size_t)(col0 + n) * H_ + k0 + k];
            Wz[n][k] = w_hh[(size_t)(256 + col0 + n) * H_ + k0 + k];
            Wn[n][k] = w_hh[(size_t)(512 + col0 + n) * H_ + k0 + k];
        }
        __syncthreads();
#pragma unroll 4
        for (int k = 0; k < 32; k++) {
            float a[4], wr[4], wz[4], wn[4];
#pragma unroll
            for (int i = 0; i < 4; i++) a[i] = As[ty * 4 + i][k];
#pragma unroll
            for (int j = 0; j < 4; j++) { wr[j] = Wr[tx * 4 + j][k]; wz[j] = Wz[tx * 4 + j][k]; wn[j] = Wn[tx * 4 + j][k]; }
#pragma unroll
            for (int i = 0; i < 4; i++)
#pragma unroll
                for (int j = 0; j < 4; j++) {
                    accR[i * 4 + j]  += a[i] * wr[j];
                    accZ[i * 4 + j]  += a[i] * wz[j];
                    accN2[i * 4 + j] += a[i] * wn[j];
                }
        }
        __syncthreads();
    }

    // ---- epilogue: gates + mask-gated state update ----
#pragma unroll
    for (int i = 0; i < 4; i++) {
        int b = row0 + ty * 4 + i;
        float o = g_obs[t * B_ + b];
#pragma unroll
        for (int j = 0; j < 4; j++) {
            int gj = col0 + tx * 4 + j;
            int idx = i * 4 + j;
            float r  = sigmoidf_(accR[idx] + b_ih[gj] + b_hh[gj]);
            float zg = sigmoidf_(accZ[idx] + b_ih[256 + gj] + b_hh[256 + gj]);
            float nn = tanhf(accN1[idx] + b_ih[512 + gj] + r * (accN2[idx] + b_hh[512 + gj]));
            float hp = h_in[(size_t)b * H_ + gj];
            float hn = (1.0f - zg) * nn + zg * hp;
            h_out[(size_t)b * H_ + gj] = o * hn + (1.0f - o) * hp;
        }
    }
}

// ---------------- generic GEMM: C = act(A @ W^T + bias [+ temb tail]) ----------------
// A: [M, lda>=K], W: [N, ldw], C: [M, ldc]. BM=128, BN=64, BK=32, 256 thr, 8x4/thread.
// If tproj_w != null: layer-1 ODE GEMM; adds sum_e temb(t)[e] * W[n, K+e] where
// temb = tproj_w @ [sin(t*k*pi)_{k=1..4}, cos(t*k*pi)_{k=1..4}] + tproj_b.
__global__ __launch_bounds__(256) void gemm_kernel(
    const float* __restrict__ A, int lda,
    const float* __restrict__ W, int ldw,
    const float* __restrict__ bias,
    float* __restrict__ C, int ldc,
    int M, int N, int K, int act,
    const float* __restrict__ tproj_w, const float* __restrict__ tproj_b, float tval)
{
    __shared__ float As[128][33];
    __shared__ float Ws[64][33];
    __shared__ float temb[8];

    int tid = threadIdx.x;
    int tx = tid & 15, ty = tid >> 4;
    int row0 = blockIdx.x * 128;
    int col0 = blockIdx.y * 64;

    if (tproj_w != nullptr && tid < 8) {
        float s = 0.f;
#pragma unroll
        for (int f = 0; f < 8; f++) {
            float arg = (f < 4) ? (tval * (float)(f + 1) * PI_F) : (tval * (float)(f - 3) * PI_F);
            float em = (f < 4) ? sinf(arg) : cosf(arg);
            s += tproj_w[tid * 8 + f] * em;
        }
        temb[tid] = s + tproj_b[tid];
    }

    float acc[32];
#pragma unroll
    for (int i = 0; i < 32; i++) acc[i] = 0.f;

    for (int k0 = 0; k0 < K; k0 += 32) {
#pragma unroll
        for (int i = 0; i < 16; i++) {
            int e = tid + i * 256;
            int m = e >> 5, k = e & 31;
            As[m][k] = A[(size_t)(row0 + m) * lda + k0 + k];
        }
#pragma unroll
        for (int i = 0; i < 8; i++) {
            int e = tid + i * 256;
            int n = e >> 5, k = e & 31;
            Ws[n][k] = W[(size_t)(col0 + n) * ldw + k0 + k];
        }
        __syncthreads();
#pragma unroll 4
        for (int k = 0; k < 32; k++) {
            float a[8], w[4];
#pragma unroll
            for (int i = 0; i < 8; i++) a[i] = As[ty * 8 + i][k];
#pragma unroll
            for (int j = 0; j < 4; j++) w[j] = Ws[tx * 4 + j][k];
#pragma unroll
            for (int i = 0; i < 8; i++)
#pragma unroll
                for (int j = 0; j < 4; j++) acc[i * 4 + j] += a[i] * w[j];
        }
        __syncthreads();
    }

#pragma unroll
    for (int j = 0; j < 4; j++) {
        int n = col0 + tx * 4 + j;
        float tadd = 0.f;
        if (tproj_w != nullptr) {
#pragma unroll
            for (int e = 0; e < 8; e++) tadd += temb[e] * W[(size_t)n * ldw + K + e];
        }
        float bb = bias[n] + tadd;
#pragma unroll
        for (int i = 0; i < 8; i++) {
            int m = row0 + ty * 8 + i;
            float v = acc[i * 4 + j] + bb;
            if (act == 1) v = tanhf(v);
            C[(size_t)m * ldc + n] = v;
        }
    }
}

// ---------------- ztmp = z + s * k ----------------
__global__ void axpy_kernel(const float* __restrict__ a, const float* __restrict__ b,
                            float s, float* __restrict__ out) {
    int i = blockIdx.x * blockDim.x + threadIdx.x;  // over (B_*L_)/4
    if (i >= (B_ * L_) / 4) return;
    float4 av = ((const float4*)a)[i];
    float4 bv = ((const float4*)b)[i];
    float4 o;
    o.x = av.x + s * bv.x; o.y = av.y + s * bv.y;
    o.z = av.z + s * bv.z; o.w = av.w + s * bv.w;
    ((float4*)out)[i] = o;
}

// ---------------- z += h/6*(k1+2k2+2k3+k4); z_traj[:, step, :] = z ----------------
__global__ void combine_kernel(float* __restrict__ z, const float* __restrict__ k1,
                               const float* __restrict__ k2, const float* __restrict__ k3,
                               const float* __restrict__ k4, float h6, int step) {
    int i = blockIdx.x * blockDim.x + threadIdx.x;
    if (i >= B_ * L_) return;
    float v = z[i] + h6 * (k1[i] + 2.0f * (k2[i] + k3[i]) + k4[i]);
    z[i] = v;
    int b = i >> 7, j = i & 127;
    g_ztraj[((size_t)b * NH_ + step) * L_ + j] = v;
}

// ---------------- split z0_out -> (mean, logvar) outputs + ODE init ----------------
__global__ void split_kernel(float* __restrict__ out_mean, float* __restrict__ out_logvar) {
    int i = blockIdx.x * blockDim.x + threadIdx.x;
    if (i >= B_ * L_) return;
    int b = i >> 7, j = i & 127;
    float m  = g_z0out[(size_t)b * (2 * L_) + j];
    float lv = g_z0out[(size_t)b * (2 * L_) + L_ + j];
    out_mean[i] = m;
    out_logvar[i] = lv;
    g_z[i] = m;
    g_ztraj[((size_t)b * NH_) * L_ + j] = m;   // z_traj[:,0,:] = z0
}

// ---------------- DeepHit head: hazard[b,i] = sigmoid(relu(z@w1^T+b1)@w2^T+b2) ----------------
__global__ __launch_bounds__(256) void head_kernel(
    const float* __restrict__ sh_w1, const float* __restrict__ sh_b1,
    const float* __restrict__ sh_w2, const float* __restrict__ sh_b2,
    float* __restrict__ hazard_out)
{
    __shared__ float w1s[32 * 129];
    __shared__ float b1s[32];
    __shared__ float w2s[32];
    __shared__ float b2s;
    __shared__ float zb[8][128];

    int tid = threadIdx.x;
#pragma unroll
    for (int i = 0; i < 16; i++) {
        int e = tid + i * 256;        // e = m*128 + k
        int m = e >> 7, k = e & 127;
        w1s[m * 129 + k] = sh_w1[e];
    }
    if (tid < 32) { b1s[tid] = sh_b1[tid]; w2s[tid] = sh_w2[tid]; }
    if (tid == 0) b2s = sh_b2[0];
    __syncthreads();

    int warp = tid >> 5, lane = tid & 31;
    int row = blockIdx.x * 8 + warp;               // over B_*NH_
    const float* zr = &g_ztraj[(size_t)row * L_];
#pragma unroll
    for (int k = lane; k < 128; k += 32) zb[warp][k] = zr[k];
    __syncwarp();

    float s = 0.f;
#pragma unroll 8
    for (int k = 0; k < 128; k++) s += zb[warp][k] * w1s[lane * 129 + k];
    float hm = fmaxf(s + b1s[lane], 0.f);
    float p = hm * w2s[lane];
#pragma unroll
    for (int o = 16; o; o >>= 1) p += __shfl_down_sync(0xffffffffu, p, o);
    if (lane == 0) hazard_out[row] = sigmoidf_(p + b2s);
}

// ---------------- survival cumprod + p_global ----------------
__global__ void surv_kernel(const float* __restrict__ hazard,
                            float* __restrict__ survival, float* __restrict__ pg) {
    int b = blockIdx.x * blockDim.x + threadIdx.x;
    if (b >= B_) return;
    float ls = 0.f, sv = 1.f;
#pragma unroll
    for (int i = 0; i < NH_; i++) {
        sv = expf(ls);
        survival[b * NH_ + i] = sv;
        ls += logf(1.0f - hazard[b * NH_ + i] + 1e-7f);
    }
    pg[b] = 1.0f - sv;
}

// ---------------- host side ----------------
static void ode_eval(const float* zin, float t, float* kout,
                     const float* w1, const float* b1, const float* w2, const float* b2,
                     const float* w3, const float* b3,
                     const float* tpw, const float* tpb,
                     float* m1, float* m2)
{
    // layer1: [B,128]@[256,136]^T (+ temb tail) -> tanh -> m1
    gemm_kernel<<<dim3(B_ / 128, HID_ / 64), 256>>>(zin, L_, w1, L_ + E_, b1, m1, HID_,
                                                    B_, HID_, L_, 1, tpw, tpb, t);
    // layer2: [B,256]@[256,256]^T -> tanh -> m2
    gemm_kernel<<<dim3(B_ / 128, HID_ / 64), 256>>>(m1, HID_, w2, HID_, b2, m2, HID_,
                                                    B_, HID_, HID_, 1, nullptr, nullptr, 0.f);
    // layer3: [B,256]@[128,256]^T -> kout
    gemm_kernel<<<dim3(B_ / 128, L_ / 64), 256>>>(m2, HID_, w3, HID_, b3, kout, L_,
                                                  B_, L_, HID_, 0, nullptr, nullptr, 0.f);
}

extern "C" void kernel_launch(void* const* d_in, const int* in_sizes, int n_in,
                              void* d_out, int out_size) {
    const float* X        = (const float*)d_in[0];
    const float* mask     = (const float*)d_in[1];
    const float* gru_w_ih = (const float*)d_in[2];
    const float* gru_w_hh = (const float*)d_in[3];
    const float* gru_b_ih = (const float*)d_in[4];
    const float* gru_b_hh = (const float*)d_in[5];
    const float* z0_w     = (const float*)d_in[6];
    const float* z0_b     = (const float*)d_in[7];
    const float* tproj_w  = (const float*)d_in[8];
    const float* tproj_b  = (const float*)d_in[9];
    const float* ode_w1   = (const float*)d_in[10];
    const float* ode_b1   = (const float*)d_in[11];
    const float* ode_w2   = (const float*)d_in[12];
    const float* ode_b2   = (const float*)d_in[13];
    const float* ode_w3   = (const float*)d_in[14];
    const float* ode_b3   = (const float*)d_in[15];
    const float* sh_w1    = (const float*)d_in[16];
    const float* sh_b1    = (const float*)d_in[17];
    const float* sh_w2    = (const float*)d_in[18];
    const float* sh_b2    = (const float*)d_in[19];

    float* out = (float*)d_out;
    // output layout: hazard[B,NH] | survival[B,NH] | z0_mean[B,L] | z0_logvar[B,L] | p_global[B]
    float* o_haz  = out;
    float* o_surv = out + (size_t)B_ * NH_;
    float* o_mean = out + (size_t)2 * B_ * NH_;
    float* o_lvar = o_mean + (size_t)B_ * L_;
    float* o_pg   = o_lvar + (size_t)B_ * L_;

    float *hA, *hB, *z0out, *z, *ztmp, *k1, *k2, *k3, *k4, *m1, *m2;
    cudaGetSymbolAddress((void**)&hA, g_hA);
    cudaGetSymbolAddress((void**)&hB, g_hB);
    cudaGetSymbolAddress((void**)&z0out, g_z0out);
    cudaGetSymbolAddress((void**)&z, g_z);
    cudaGetSymbolAddress((void**)&ztmp, g_ztmp);
    cudaGetSymbolAddress((void**)&k1, g_k1);
    cudaGetSymbolAddress((void**)&k2, g_k2);
    cudaGetSymbolAddress((void**)&k3, g_k3);
    cudaGetSymbolAddress((void**)&k4, g_k4);
    cudaGetSymbolAddress((void**)&m1, g_m1);
    cudaGetSymbolAddress((void**)&m2, g_m2);

    // ---- GRU encoder (reversed time) ----
    cudaMemsetAsync(hA, 0, (size_t)B_ * H_ * sizeof(float), 0);
    obs_kernel<<<(B_ * T_ + 255) / 256, 256>>>(mask);

    float* hin = hA;
    float* hout = hB;
    for (int t = T_ - 1; t >= 0; t--) {
        gru_step_kernel<<<dim3(B_ / 64, H_ / 64), 256>>>(X, mask, gru_w_ih, gru_w_hh,
                                                         gru_b_ih, gru_b_hh, hin, hout, t);
        float* tmp = hin; hin = hout; hout = tmp;
    }
    // final hidden state is in hin

    // ---- z0 head: [B,256]@[256,256]^T ----
    gemm_kernel<<<dim3(B_ / 128, (2 * L_) / 64), 256>>>(hin, H_, z0_w, H_, z0_b, z0out, 2 * L_,
                                                        B_, 2 * L_, H_, 0, nullptr, nullptr, 0.f);
    split_kernel<<<(B_ * L_ + 255) / 256, 256>>>(o_mean, o_lvar);

    // ---- ODE: fixed-step RK4, one step per output interval ----
    for (int i = 0; i < NH_ - 1; i++) {
        float t0 = (float)i / (float)(NH_ - 1);
        float t1 = (float)(i + 1) / (float)(NH_ - 1);
        float h = t1 - t0;
        float tm = 0.5f * (t0 + t1);

        ode_eval(z, t0, k1, ode_w1, ode_b1, ode_w2, ode_b2, ode_w3, ode_b3, tproj_w, tproj_b, m1, m2);
        axpy_kernel<<<(B_ * L_ / 4 + 255) / 256, 256>>>(z, k1, 0.5f * h, ztmp);
        ode_eval(ztmp, tm, k2, ode_w1, ode_b1, ode_w2, ode_b2, ode_w3, ode_b3, tproj_w, tproj_b, m1, m2);
        axpy_kernel<<<(B_ * L_ / 4 + 255) / 256, 256>>>(z, k2, 0.5f * h, ztmp);
        ode_eval(ztmp, tm, k3, ode_w1, ode_b1, ode_w2, ode_b2, ode_w3, ode_b3, tproj_w, tproj_b, m1, m2);
        axpy_kernel<<<(B_ * L_ / 4 + 255) / 256, 256>>>(z, k3, h, ztmp);
        ode_eval(ztmp, t1, k4, ode_w1, ode_b1, ode_w2, ode_b2, ode_w3, ode_b3, tproj_w, tproj_b, m1, m2);
        combine_kernel<<<(B_ * L_ + 255) / 256, 256>>>(z, k1, k2, k3, k4, h / 6.0f, i + 1);
    }

    // ---- DeepHit head + survival ----
    head_kernel<<<(B_ * NH_) / 8, 256>>>(sh_w1, sh_b1, sh_w2, sh_b2, o_haz);
    surv_kernel<<<(B_ + 255) / 256, 256>>>(o_haz, o_surv, o_pg);
}

// round 5
// speedup vs baseline: 1.9692x; 1.9692x over previous
#include <cuda_runtime.h>
#include <math.h>

#define B_   4096
#define T_   48
#define D_   32
#define H_   256
#define G3_  768          // 3*H
#define L_   128
#define HID_ 256
#define E_   8
#define NH_  48
#define NS_  12           // RK4 steps over [0,1]
#define BL_  (B_ * L_)
#define PI_F 3.14159265358979323846f

// ---------------- scratch (device globals; no allocation allowed) ----------------
__device__ float g_hA[B_ * H_];
__device__ float g_hB[B_ * H_];
__device__ float g_obs[T_ * B_];
__device__ float g_gih[(size_t)T_ * B_ * G3_];   // precomputed inp@W_ih^T + b_ih, [t][b][768]
__device__ float g_z0out[B_ * 2 * L_];
__device__ float g_k2[BL_];
__device__ float g_k3[BL_];
__device__ float g_m1[B_ * HID_];
__device__ float g_m2[B_ * HID_];
__device__ float g_znode[(NS_ + 1) * BL_];   // z at RK4 nodes
__device__ float g_fnode[(NS_ + 1) * BL_];   // f(z,t) at RK4 nodes

__device__ __forceinline__ float sigmoidf_(float x) {
    return 1.0f / (1.0f + expf(-x));
}

// ---------------- obs mask: any_obs[t,b] = (sum_k mask[b,t,k]) > 0 ----------------
__global__ void obs_kernel(const float* __restrict__ mask) {
    int i = blockIdx.x * blockDim.x + threadIdx.x;  // over B_*T_
    if (i >= B_ * T_) return;
    int b = i / T_, t = i % T_;
    const float* mp = mask + (size_t)i * D_;
    float s = 0.f;
#pragma unroll
    for (int k = 0; k < D_; k++) s += mp[k];
    g_obs[t * B_ + b] = (s > 0.f) ? 1.0f : 0.0f;
}

// ---------------- gih precompute: for all (b,t): gih = [X,mask] @ w_ih^T + b_ih ----------------
// A row index r = b*T + t (X is [B,T,32] so row r is contiguous at X + r*32).
// Output stored [t][b][768] for coalesced per-step access.
__global__ __launch_bounds__(256) void gih_kernel(
    const float* __restrict__ X, const float* __restrict__ mask,
    const float* __restrict__ w_ih, const float* __restrict__ b_ih)
{
    __shared__ float As[64][33];
    __shared__ float Ws[64][33];

    int tid = threadIdx.x;
    int tx = tid & 15, ty = tid >> 4;
    int row0 = blockIdx.x * 64;   // over r = b*T + t
    int col0 = blockIdx.y * 64;   // over 768

    float acc[16];
#pragma unroll
    for (int i = 0; i < 16; i++) acc[i] = 0.f;

    for (int c = 0; c < 2; c++) {
        const float* Ab = (c == 0) ? X : mask;
        int k0 = c * 32;
#pragma unroll
        for (int i = 0; i < 8; i++) {
            int e = tid + i * 256;
            int m = e >> 5, k = e & 31;
            As[m][k] = Ab[(size_t)(row0 + m) * D_ + k];
        }
#pragma unroll
        for (int i = 0; i < 8; i++) {
            int e = tid + i * 256;
            int n = e >> 5, k = e & 31;
            Ws[n][k] = w_ih[(size_t)(col0 + n) * 64 + k0 + k];
        }
        __syncthreads();
#pragma unroll 8
        for (int k = 0; k < 32; k++) {
            float a[4], w[4];
#pragma unroll
            for (int i = 0; i < 4; i++) a[i] = As[ty * 4 + i][k];
#pragma unroll
            for (int j = 0; j < 4; j++) w[j] = Ws[tx * 4 + j][k];
#pragma unroll
            for (int i = 0; i < 4; i++)
#pragma unroll
                for (int j = 0; j < 4; j++) acc[i * 4 + j] += a[i] * w[j];
        }
        __syncthreads();
    }

#pragma unroll
    for (int i = 0; i < 4; i++) {
        int r = row0 + ty * 4 + i;
        int b = r / T_, t = r - b * T_;
        size_t ob = ((size_t)t * B_ + b) * G3_;
#pragma unroll
        for (int j = 0; j < 4; j++) {
            int n = col0 + tx * 4 + j;
            g_gih[ob + n] = acc[i * 4 + j] + b_ih[n];
        }
    }
}

// ---------------- one GRU step: only h @ w_hh^T (K=256); ih gates read precomputed ----------------
__global__ __launch_bounds__(256) void gru_step_kernel(
    const float* __restrict__ w_hh, const float* __restrict__ b_hh,
    const float* __restrict__ h_in, float* __restrict__ h_out, int t)
{
    __shared__ float As[64][33];
    __shared__ float Wr[64][33];
    __shared__ float Wz[64][33];
    __shared__ float Wn[64][33];

    int tid = threadIdx.x;
    int tx = tid & 15, ty = tid >> 4;
    int row0 = blockIdx.x * 64;
    int col0 = blockIdx.y * 64;

    float accR[16], accZ[16], accN[16];
#pragma unroll
    for (int i = 0; i < 16; i++) { accR[i] = 0.f; accZ[i] = 0.f; accN[i] = 0.f; }

    for (int c = 0; c < 8; c++) {
        int k0 = c * 32;
#pragma unroll
        for (int i = 0; i < 8; i++) {
            int e = tid + i * 256;
            int m = e >> 5, k = e & 31;
            As[m][k] = h_in[(size_t)(row0 + m) * H_ + k0 + k];
        }
#pragma unroll
        for (int i = 0; i < 8; i++) {
            int e = tid + i * 256;
            int n = e >> 5, k = e & 31;
            Wr[n][k] = w_hh[(size_t)(col0 + n) * H_ + k0 + k];
            Wz[n][k] = w_hh[(size_t)(256 + col0 + n) * H_ + k0 + k];
            Wn[n][k] = w_hh[(size_t)(512 + col0 + n) * H_ + k0 + k];
        }
        __syncthreads();
#pragma unroll 4
        for (int k = 0; k < 32; k++) {
            float a[4], wr[4], wz[4], wn[4];
#pragma unroll
            for (int i = 0; i < 4; i++) a[i] = As[ty * 4 + i][k];
#pragma unroll
            for (int j = 0; j < 4; j++) { wr[j] = Wr[tx * 4 + j][k]; wz[j] = Wz[tx * 4 + j][k]; wn[j] = Wn[tx * 4 + j][k]; }
#pragma unroll
            for (int i = 0; i < 4; i++)
#pragma unroll
                for (int j = 0; j < 4; j++) {
                    accR[i * 4 + j] += a[i] * wr[j];
                    accZ[i * 4 + j] += a[i] * wz[j];
                    accN[i * 4 + j] += a[i] * wn[j];
                }
        }
        __syncthreads();
    }

    // ---- epilogue: gates + mask-gated state update ----
#pragma unroll
    for (int i = 0; i < 4; i++) {
        int b = row0 + ty * 4 + i;
        float o = g_obs[t * B_ + b];
        const float* gih = &g_gih[((size_t)t * B_ + b) * G3_];
#pragma unroll
        for (int j = 0; j < 4; j++) {
            int gj = col0 + tx * 4 + j;
            int idx = i * 4 + j;
            float r  = sigmoidf_(accR[idx] + gih[gj] + b_hh[gj]);
            float zg = sigmoidf_(accZ[idx] + gih[256 + gj] + b_hh[256 + gj]);
            float nn = tanhf(gih[512 + gj] + r * (accN[idx] + b_hh[512 + gj]));
            float hp = h_in[(size_t)b * H_ + gj];
            float hn = (1.0f - zg) * nn + zg * hp;
            h_out[(size_t)b * H_ + gj] = o * hn + (1.0f - o) * hp;
        }
    }
}

// ---------------- GEMM 64x64: C = act((A + ascale*A2) @ W^T + bias [+ temb tail]) ----------------
// Optional RK4-combine epilogue: C = ep_z + ep_h6*(ep_k1 + 2*ep_k2 + 2*ep_k3 + (acc+bias))
__global__ __launch_bounds__(256) void gemm64_kernel(
    const float* __restrict__ A, const float* __restrict__ A2, float ascale, int lda,
    const float* __restrict__ W, int ldw,
    const float* __restrict__ bias,
    float* __restrict__ C, int ldc,
    int M, int N, int K, int act,
    const float* __restrict__ tproj_w, const float* __restrict__ tproj_b, float tval,
    const float* __restrict__ ep_z, const float* __restrict__ ep_k1,
    const float* __restrict__ ep_k2, const float* __restrict__ ep_k3, float ep_h6)
{
    __shared__ float As[64][33];
    __shared__ float Ws[64][33];
    __shared__ float temb[8];

    int tid = threadIdx.x;
    int tx = tid & 15, ty = tid >> 4;
    int row0 = blockIdx.x * 64;
    int col0 = blockIdx.y * 64;

    if (tproj_w != nullptr && tid < 8) {
        float s = 0.f;
#pragma unroll
        for (int f = 0; f < 8; f++) {
            float arg = (f < 4) ? (tval * (float)(f + 1) * PI_F) : (tval * (float)(f - 3) * PI_F);
            float em = (f < 4) ? sinf(arg) : cosf(arg);
            s += tproj_w[tid * 8 + f] * em;
        }
        temb[tid] = s + tproj_b[tid];
    }

    float acc[16];
#pragma unroll
    for (int i = 0; i < 16; i++) acc[i] = 0.f;

    for (int k0 = 0; k0 < K; k0 += 32) {
#pragma unroll
        for (int i = 0; i < 8; i++) {
            int e = tid + i * 256;
            int m = e >> 5, k = e & 31;
            size_t gi = (size_t)(row0 + m) * lda + k0 + k;
            float v = A[gi];
            if (A2 != nullptr) v += ascale * A2[gi];
            As[m][k] = v;
        }
#pragma unroll
        for (int i = 0; i < 8; i++) {
            int e = tid + i * 256;
            int n = e >> 5, k = e & 31;
            Ws[n][k] = W[(size_t)(col0 + n) * ldw + k0 + k];
        }
        __syncthreads();
#pragma unroll 8
        for (int k = 0; k < 32; k++) {
            float a[4], w[4];
#pragma unroll
            for (int i = 0; i < 4; i++) a[i] = As[ty * 4 + i][k];
#pragma unroll
            for (int j = 0; j < 4; j++) w[j] = Ws[tx * 4 + j][k];
#pragma unroll
            for (int i = 0; i < 4; i++)
#pragma unroll
                for (int j = 0; j < 4; j++) acc[i * 4 + j] += a[i] * w[j];
        }
        __syncthreads();
    }

#pragma unroll
    for (int j = 0; j < 4; j++) {
        int n = col0 + tx * 4 + j;
        float tadd = 0.f;
        if (tproj_w != nullptr) {
#pragma unroll
            for (int e = 0; e < 8; e++) tadd += temb[e] * W[(size_t)n * ldw + K + e];
        }
        float bb = bias[n] + tadd;
#pragma unroll
        for (int i = 0; i < 4; i++) {
            int m = row0 + ty * 4 + i;
            float v = acc[i * 4 + j] + bb;
            size_t oi = (size_t)m * ldc + n;
            if (ep_z != nullptr) {
                v = ep_z[oi] + ep_h6 * (ep_k1[oi] + 2.0f * (ep_k2[oi] + ep_k3[oi]) + v);
            } else if (act == 1) {
                v = tanhf(v);
            }
            C[oi] = v;
        }
    }
}

// ---------------- split z0_out -> (mean, logvar) outputs + ODE init node ----------------
__global__ void split_kernel(float* __restrict__ out_mean, float* __restrict__ out_logvar) {
    int i = blockIdx.x * blockDim.x + threadIdx.x;
    if (i >= BL_) return;
    int b = i >> 7, j = i & 127;
    float m  = g_z0out[(size_t)b * (2 * L_) + j];
    float lv = g_z0out[(size_t)b * (2 * L_) + L_ + j];
    out_mean[i] = m;
    out_logvar[i] = lv;
    g_znode[i] = m;           // znode[0] = z0
}

// ---------------- DeepHit head with fused Hermite dense output ----------------
__global__ __launch_bounds__(256) void head_kernel(
    const float* __restrict__ sh_w1, const float* __restrict__ sh_b1,
    const float* __restrict__ sh_w2, const float* __restrict__ sh_b2,
    float* __restrict__ hazard_out)
{
    __shared__ float w1s[32 * 129];
    __shared__ float b1s[32];
    __shared__ float w2s[32];
    __shared__ float b2s;
    __shared__ float zb[8][128];

    int tid = threadIdx.x;
#pragma unroll
    for (int i = 0; i < 16; i++) {
        int e = tid + i * 256;        // e = m*128 + k
        int m = e >> 7, k = e & 127;
        w1s[m * 129 + k] = sh_w1[e];
    }
    if (tid < 32) { b1s[tid] = sh_b1[tid]; w2s[tid] = sh_w2[tid]; }
    if (tid == 0) b2s = sh_b2[0];
    __syncthreads();

    int warp = tid >> 5, lane = tid & 31;
    int row = blockIdx.x * 8 + warp;               // over B_*NH_
    int b = row / NH_, j = row - b * NH_;

    float t = (float)j / (float)(NH_ - 1);
    float ts = t * (float)NS_;
    int iv = (int)ts; if (iv > NS_ - 1) iv = NS_ - 1;
    float th = ts - (float)iv;
    float th2 = th * th, th3 = th2 * th;
    float h00 = 2.f * th3 - 3.f * th2 + 1.f;
    float h10 = th3 - 2.f * th2 + th;
    float h01 = -2.f * th3 + 3.f * th2;
    float h11 = th3 - th2;
    float hstep = 1.0f / (float)NS_;

    const float* z0r = g_znode + (size_t)iv * BL_ + (size_t)b * L_;
    const float* z1r = z0r + BL_;
    const float* f0r = g_fnode + (size_t)iv * BL_ + (size_t)b * L_;
    const float* f1r = f0r + BL_;
#pragma unroll
    for (int k = lane; k < 128; k += 32) {
        zb[warp][k] = h00 * z0r[k] + h01 * z1r[k] + hstep * (h10 * f0r[k] + h11 * f1r[k]);
    }
    __syncwarp();

    float s = 0.f;
#pragma unroll 8
    for (int k = 0; k < 128; k++) s += zb[warp][k] * w1s[lane * 129 + k];
    float hm = fmaxf(s + b1s[lane], 0.f);
    float p = hm * w2s[lane];
#pragma unroll
    for (int o = 16; o; o >>= 1) p += __shfl_down_sync(0xffffffffu, p, o);
    if (lane == 0) hazard_out[row] = sigmoidf_(p + b2s);
}

// ---------------- survival cumprod + p_global ----------------
__global__ void surv_kernel(const float* __restrict__ hazard,
                            float* __restrict__ survival, float* __restrict__ pg) {
    int b = blockIdx.x * blockDim.x + threadIdx.x;
    if (b >= B_) return;
    float ls = 0.f, sv = 1.f;
#pragma unroll
    for (int i = 0; i < NH_; i++) {
        sv = expf(ls);
        survival[b * NH_ + i] = sv;
        ls += logf(1.0f - hazard[b * NH_ + i] + 1e-7f);
    }
    pg[b] = 1.0f - sv;
}

// ---------------- host side ----------------
struct OdeW {
    const float *w1, *b1, *w2, *b2, *w3, *b3, *tpw, *tpb;
    float *m1, *m2;
};

// f(zin + s*zin2, t) -> kout ; optional RK4-combine epilogue on layer 3
static void ode_eval(const float* zin, const float* zin2, float s, float t, float* kout,
                     const OdeW& o,
                     const float* ep_z = nullptr, const float* ep_k1 = nullptr,
                     const float* ep_k2 = nullptr, const float* ep_k3 = nullptr,
                     float ep_h6 = 0.f)
{
    gemm64_kernel<<<dim3(B_ / 64, HID_ / 64), 256>>>(zin, zin2, s, L_, o.w1, L_ + E_, o.b1,
        o.m1, HID_, B_, HID_, L_, 1, o.tpw, o.tpb, t,
        nullptr, nullptr, nullptr, nullptr, 0.f);
    gemm64_kernel<<<dim3(B_ / 64, HID_ / 64), 256>>>(o.m1, nullptr, 0.f, HID_, o.w2, HID_, o.b2,
        o.m2, HID_, B_, HID_, HID_, 1, nullptr, nullptr, 0.f,
        nullptr, nullptr, nullptr, nullptr, 0.f);
    gemm64_kernel<<<dim3(B_ / 64, L_ / 64), 256>>>(o.m2, nullptr, 0.f, HID_, o.w3, HID_, o.b3,
        kout, L_, B_, L_, HID_, 0, nullptr, nullptr, 0.f,
        ep_z, ep_k1, ep_k2, ep_k3, ep_h6);
}

extern "C" void kernel_launch(void* const* d_in, const int* in_sizes, int n_in,
                              void* d_out, int out_size) {
    const float* X        = (const float*)d_in[0];
    const float* mask     = (const float*)d_in[1];
    const float* gru_w_ih = (const float*)d_in[2];
    const float* gru_w_hh = (const float*)d_in[3];
    const float* gru_b_ih = (const float*)d_in[4];
    const float* gru_b_hh = (const float*)d_in[5];
    const float* z0_w     = (const float*)d_in[6];
    const float* z0_b     = (const float*)d_in[7];
    const float* tproj_w  = (const float*)d_in[8];
    const float* tproj_b  = (const float*)d_in[9];
    const float* ode_w1   = (const float*)d_in[10];
    const float* ode_b1   = (const float*)d_in[11];
    const float* ode_w2   = (const float*)d_in[12];
    const float* ode_b2   = (const float*)d_in[13];
    const float* ode_w3   = (const float*)d_in[14];
    const float* ode_b3   = (const float*)d_in[15];
    const float* sh_w1    = (const float*)d_in[16];
    const float* sh_b1    = (const float*)d_in[17];
    const float* sh_w2    = (const float*)d_in[18];
    const float* sh_b2    = (const float*)d_in[19];

    float* out = (float*)d_out;
    // output layout: hazard[B,NH] | survival[B,NH] | z0_mean[B,L] | z0_logvar[B,L] | p_global[B]
    float* o_haz  = out;
    float* o_surv = out + (size_t)B_ * NH_;
    float* o_mean = out + (size_t)2 * B_ * NH_;
    float* o_lvar = o_mean + (size_t)BL_;
    float* o_pg   = o_lvar + (size_t)BL_;

    float *hA, *hB, *z0out, *k2, *k3, *m1, *m2, *znode, *fnode;
    cudaGetSymbolAddress((void**)&hA, g_hA);
    cudaGetSymbolAddress((void**)&hB, g_hB);
    cudaGetSymbolAddress((void**)&z0out, g_z0out);
    cudaGetSymbolAddress((void**)&k2, g_k2);
    cudaGetSymbolAddress((void**)&k3, g_k3);
    cudaGetSymbolAddress((void**)&m1, g_m1);
    cudaGetSymbolAddress((void**)&m2, g_m2);
    cudaGetSymbolAddress((void**)&znode, g_znode);
    cudaGetSymbolAddress((void**)&fnode, g_fnode);

    OdeW ow{ode_w1, ode_b1, ode_w2, ode_b2, ode_w3, ode_b3, tproj_w, tproj_b, m1, m2};

    // ---- GRU encoder (reversed time) ----
    cudaMemsetAsync(hA, 0, (size_t)B_ * H_ * sizeof(float), 0);
    obs_kernel<<<(B_ * T_ + 255) / 256, 256>>>(mask);
    gih_kernel<<<dim3((B_ * T_) / 64, G3_ / 64), 256>>>(X, mask, gru_w_ih, gru_b_ih);

    float* hin = hA;
    float* hout = hB;
    for (int t = T_ - 1; t >= 0; t--) {
        gru_step_kernel<<<dim3(B_ / 64, H_ / 64), 256>>>(gru_w_hh, gru_b_hh, hin, hout, t);
        float* tmp = hin; hin = hout; hout = tmp;
    }

    // ---- z0 head: [B,256]@[256,256]^T ----
    gemm64_kernel<<<dim3(B_ / 64, (2 * L_) / 64), 256>>>(hin, nullptr, 0.f, H_, z0_w, H_, z0_b,
        z0out, 2 * L_, B_, 2 * L_, H_, 0, nullptr, nullptr, 0.f,
        nullptr, nullptr, nullptr, nullptr, 0.f);
    split_kernel<<<(BL_ + 255) / 256, 256>>>(o_mean, o_lvar);

    // ---- ODE: NS_ fixed RK4 steps; nodes (z_i, f_i) kept for Hermite dense output ----
    const float h = 1.0f / (float)NS_;
    for (int i = 0; i < NS_; i++) {
        float t0 = (float)i * h;
        float tm = t0 + 0.5f * h;
        float t1 = t0 + h;
        float* zi = znode + (size_t)i * BL_;
        float* fi = fnode + (size_t)i * BL_;       // k1 lives here
        float* zn = znode + (size_t)(i + 1) * BL_;

        ode_eval(zi, nullptr, 0.f, t0, fi, ow);                          // k1 = f(z_i, t0)
        ode_eval(zi, fi, 0.5f * h, tm, k2, ow);                          // k2
        ode_eval(zi, k2, 0.5f * h, tm, k3, ow);                          // k3
        ode_eval(zi, k3, h, t1, zn, ow, zi, fi, k2, k3, h / 6.0f);       // k4 + combine -> z_{i+1}
    }
    // f at the final node (needed by Hermite on the last interval)
    ode_eval(znode + (size_t)NS_ * BL_, nullptr, 0.f, 1.0f, fnode + (size_t)NS_ * BL_, ow);

    // ---- DeepHit head (with fused dense-output interpolation) + survival ----
    head_kernel<<<(B_ * NH_) / 8, 256>>>(sh_w1, sh_b1, sh_w2, sh_b2, o_haz);
    surv_kernel<<<(B_ + 255) / 256, 256>>>(o_haz, o_surv, o_pg);
}

// round 6
// speedup vs baseline: 2.3428x; 1.1898x over previous
#include <cuda_runtime.h>
#include <math.h>

#define B_   4096
#define T_   48
#define D_   32
#define H_   256
#define G3_  768          // 3*H
#define L_   128
#define HID_ 256
#define E_   8
#define NH_  48
#define NS_  12           // RK4 steps over [0,1]
#define BL_  (B_ * L_)
#define PI_F 3.14159265358979323846f

// ---------------- scratch (device globals; no allocation allowed) ----------------
__device__ float g_hA[B_ * H_];
__device__ float g_hB[B_ * H_];
__device__ float g_obs[T_ * B_];
__device__ float g_gih[(size_t)T_ * B_ * G3_];   // precomputed inp@W_ih^T + b_ih, [t][b][768]
__device__ float g_z0out[B_ * 2 * L_];
__device__ float g_k2[BL_];
__device__ float g_k3[BL_];
__device__ float g_m1[B_ * HID_];
__device__ float g_m2[B_ * HID_];
__device__ float g_znode[(NS_ + 1) * BL_];   // z at RK4 nodes
__device__ float g_fnode[(NS_ + 1) * BL_];   // f(z,t) at RK4 nodes

__device__ __forceinline__ float sigmoidf_(float x) {
    return 1.0f / (1.0f + expf(-x));
}

// ---------------- obs mask: any_obs[t,b] = (sum_k mask[b,t,k]) > 0 ----------------
__global__ void obs_kernel(const float* __restrict__ mask) {
    int i = blockIdx.x * blockDim.x + threadIdx.x;  // over B_*T_
    if (i >= B_ * T_) return;
    int b = i / T_, t = i % T_;
    const float* mp = mask + (size_t)i * D_;
    float s = 0.f;
#pragma unroll
    for (int k = 0; k < D_; k++) s += mp[k];
    g_obs[t * B_ + b] = (s > 0.f) ? 1.0f : 0.0f;
}

// ---------------- gih precompute: for all (b,t): gih = [X,mask] @ w_ih^T + b_ih ----------------
// BM=128, BN=64. Row r = b*T + t. Output stored [t][b][768].
__global__ __launch_bounds__(256) void gih_kernel(
    const float* __restrict__ X, const float* __restrict__ mask,
    const float* __restrict__ w_ih, const float* __restrict__ b_ih)
{
    __shared__ float As[128][33];
    __shared__ float Ws[64][33];

    int tid = threadIdx.x;
    int tx = tid & 15, ty = tid >> 4;
    int row0 = blockIdx.x * 128;  // over r = b*T + t
    int col0 = blockIdx.y * 64;   // over 768

    float acc[32];
#pragma unroll
    for (int i = 0; i < 32; i++) acc[i] = 0.f;

    for (int c = 0; c < 2; c++) {
        const float* Ab = (c == 0) ? X : mask;
        int k0 = c * 32;
#pragma unroll
        for (int i = 0; i < 16; i++) {
            int e = tid + i * 256;
            int m = e >> 5, k = e & 31;
            As[m][k] = Ab[(size_t)(row0 + m) * D_ + k];
        }
#pragma unroll
        for (int i = 0; i < 8; i++) {
            int e = tid + i * 256;
            int n = e >> 5, k = e & 31;
            Ws[n][k] = w_ih[(size_t)(col0 + n) * 64 + k0 + k];
        }
        __syncthreads();
#pragma unroll 4
        for (int k = 0; k < 32; k++) {
            float a[8], w[4];
#pragma unroll
            for (int i = 0; i < 8; i++) a[i] = As[ty * 8 + i][k];
#pragma unroll
            for (int j = 0; j < 4; j++) w[j] = Ws[tx * 4 + j][k];
#pragma unroll
            for (int i = 0; i < 8; i++)
#pragma unroll
                for (int j = 0; j < 4; j++) acc[i * 4 + j] += a[i] * w[j];
        }
        __syncthreads();
    }

#pragma unroll
    for (int i = 0; i < 8; i++) {
        int r = row0 + ty * 8 + i;
        int b = r / T_, t = r - b * T_;
        size_t ob = ((size_t)t * B_ + b) * G3_;
#pragma unroll
        for (int j = 0; j < 4; j++) {
            int n = col0 + tx * 4 + j;
            g_gih[ob + n] = acc[i * 4 + j] + b_ih[n];
        }
    }
}

// ---------------- one GRU step: h @ w_hh^T (K=256), BM=128 x BN=64, single wave ----------------
__global__ __launch_bounds__(256) void gru_step_kernel(
    const float* __restrict__ w_hh, const float* __restrict__ b_hh,
    const float* __restrict__ h_in, float* __restrict__ h_out, int t)
{
    __shared__ float As[128][33];
    __shared__ float Wr[64][33];
    __shared__ float Wz[64][33];
    __shared__ float Wn[64][33];

    int tid = threadIdx.x;
    int tx = tid & 15, ty = tid >> 4;
    int row0 = blockIdx.x * 128;
    int col0 = blockIdx.y * 64;

    float accR[32], accZ[32], accN[32];
#pragma unroll
    for (int i = 0; i < 32; i++) { accR[i] = 0.f; accZ[i] = 0.f; accN[i] = 0.f; }

    for (int c = 0; c < 8; c++) {
        int k0 = c * 32;
#pragma unroll
        for (int i = 0; i < 16; i++) {
            int e = tid + i * 256;
            int m = e >> 5, k = e & 31;
            As[m][k] = h_in[(size_t)(row0 + m) * H_ + k0 + k];
        }
#pragma unroll
        for (int i = 0; i < 8; i++) {
            int e = tid + i * 256;
            int n = e >> 5, k = e & 31;
            Wr[n][k] = w_hh[(size_t)(col0 + n) * H_ + k0 + k];
            Wz[n][k] = w_hh[(size_t)(256 + col0 + n) * H_ + k0 + k];
            Wn[n][k] = w_hh[(size_t)(512 + col0 + n) * H_ + k0 + k];
        }
        __syncthreads();
#pragma unroll 2
        for (int k = 0; k < 32; k++) {
            float a[8], wr[4], wz[4], wn[4];
#pragma unroll
            for (int i = 0; i < 8; i++) a[i] = As[ty * 8 + i][k];
#pragma unroll
            for (int j = 0; j < 4; j++) { wr[j] = Wr[tx * 4 + j][k]; wz[j] = Wz[tx * 4 + j][k]; wn[j] = Wn[tx * 4 + j][k]; }
#pragma unroll
            for (int i = 0; i < 8; i++)
#pragma unroll
                for (int j = 0; j < 4; j++) {
                    accR[i * 4 + j] += a[i] * wr[j];
                    accZ[i * 4 + j] += a[i] * wz[j];
                    accN[i * 4 + j] += a[i] * wn[j];
                }
        }
        __syncthreads();
    }

    // ---- epilogue: gates + mask-gated state update ----
#pragma unroll
    for (int i = 0; i < 8; i++) {
        int b = row0 + ty * 8 + i;
        float o = g_obs[t * B_ + b];
        const float* gih = &g_gih[((size_t)t * B_ + b) * G3_];
#pragma unroll
        for (int j = 0; j < 4; j++) {
            int gj = col0 + tx * 4 + j;
            int idx = i * 4 + j;
            float r  = sigmoidf_(accR[idx] + gih[gj] + b_hh[gj]);
            float zg = sigmoidf_(accZ[idx] + gih[256 + gj] + b_hh[256 + gj]);
            float nn = tanhf(gih[512 + gj] + r * (accN[idx] + b_hh[512 + gj]));
            float hp = h_in[(size_t)b * H_ + gj];
            float hn = (1.0f - zg) * nn + zg * hp;
            h_out[(size_t)b * H_ + gj] = o * hn + (1.0f - o) * hp;
        }
    }
}

// ---------------- GEMM 128x64: C = act((A + ascale*A2) @ W^T + bias [+ temb tail]) ----------------
__global__ __launch_bounds__(256) void gemm128_kernel(
    const float* __restrict__ A, const float* __restrict__ A2, float ascale, int lda,
    const float* __restrict__ W, int ldw,
    const float* __restrict__ bias,
    float* __restrict__ C, int ldc,
    int M, int N, int K, int act,
    const float* __restrict__ tproj_w, const float* __restrict__ tproj_b, float tval)
{
    __shared__ float As[128][33];
    __shared__ float Ws[64][33];
    __shared__ float temb[8];

    int tid = threadIdx.x;
    int tx = tid & 15, ty = tid >> 4;
    int row0 = blockIdx.x * 128;
    int col0 = blockIdx.y * 64;

    if (tproj_w != nullptr && tid < 8) {
        float s = 0.f;
#pragma unroll
        for (int f = 0; f < 8; f++) {
            float arg = (f < 4) ? (tval * (float)(f + 1) * PI_F) : (tval * (float)(f - 3) * PI_F);
            float em = (f < 4) ? sinf(arg) : cosf(arg);
            s += tproj_w[tid * 8 + f] * em;
        }
        temb[tid] = s + tproj_b[tid];
    }

    float acc[32];
#pragma unroll
    for (int i = 0; i < 32; i++) acc[i] = 0.f;

    for (int k0 = 0; k0 < K; k0 += 32) {
#pragma unroll
        for (int i = 0; i < 16; i++) {
            int e = tid + i * 256;
            int m = e >> 5, k = e & 31;
            size_t gi = (size_t)(row0 + m) * lda + k0 + k;
            float v = A[gi];
            if (A2 != nullptr) v += ascale * A2[gi];
            As[m][k] = v;
        }
#pragma unroll
        for (int i = 0; i < 8; i++) {
            int e = tid + i * 256;
            int n = e >> 5, k = e & 31;
            Ws[n][k] = W[(size_t)(col0 + n) * ldw + k0 + k];
        }
        __syncthreads();
#pragma unroll 4
        for (int k = 0; k < 32; k++) {
            float a[8], w[4];
#pragma unroll
            for (int i = 0; i < 8; i++) a[i] = As[ty * 8 + i][k];
#pragma unroll
            for (int j = 0; j < 4; j++) w[j] = Ws[tx * 4 + j][k];
#pragma unroll
            for (int i = 0; i < 8; i++)
#pragma unroll
                for (int j = 0; j < 4; j++) acc[i * 4 + j] += a[i] * w[j];
        }
        __syncthreads();
    }

#pragma unroll
    for (int j = 0; j < 4; j++) {
        int n = col0 + tx * 4 + j;
        float tadd = 0.f;
        if (tproj_w != nullptr) {
#pragma unroll
            for (int e = 0; e < 8; e++) tadd += temb[e] * W[(size_t)n * ldw + K + e];
        }
        float bb = bias[n] + tadd;
#pragma unroll
        for (int i = 0; i < 8; i++) {
            int m = row0 + ty * 8 + i;
            float v = acc[i * 4 + j] + bb;
            if (act == 1) v = tanhf(v);
            C[(size_t)m * ldc + n] = v;
        }
    }
}

// ---------------- GEMM 64x64 (layer-3 path, with RK4-combine epilogue) ----------------
__global__ __launch_bounds__(256) void gemm64_kernel(
    const float* __restrict__ A, int lda,
    const float* __restrict__ W, int ldw,
    const float* __restrict__ bias,
    float* __restrict__ C, int ldc,
    int M, int N, int K, int act,
    const float* __restrict__ ep_z, const float* __restrict__ ep_k1,
    const float* __restrict__ ep_k2, const float* __restrict__ ep_k3, float ep_h6)
{
    __shared__ float As[64][33];
    __shared__ float Ws[64][33];

    int tid = threadIdx.x;
    int tx = tid & 15, ty = tid >> 4;
    int row0 = blockIdx.x * 64;
    int col0 = blockIdx.y * 64;

    float acc[16];
#pragma unroll
    for (int i = 0; i < 16; i++) acc[i] = 0.f;

    for (int k0 = 0; k0 < K; k0 += 32) {
#pragma unroll
        for (int i = 0; i < 8; i++) {
            int e = tid + i * 256;
            int m = e >> 5, k = e & 31;
            As[m][k] = A[(size_t)(row0 + m) * lda + k0 + k];
        }
#pragma unroll
        for (int i = 0; i < 8; i++) {
            int e = tid + i * 256;
            int n = e >> 5, k = e & 31;
            Ws[n][k] = W[(size_t)(col0 + n) * ldw + k0 + k];
        }
        __syncthreads();
#pragma unroll 8
        for (int k = 0; k < 32; k++) {
            float a[4], w[4];
#pragma unroll
            for (int i = 0; i < 4; i++) a[i] = As[ty * 4 + i][k];
#pragma unroll
            for (int j = 0; j < 4; j++) w[j] = Ws[tx * 4 + j][k];
#pragma unroll
            for (int i = 0; i < 4; i++)
#pragma unroll
                for (int j = 0; j < 4; j++) acc[i * 4 + j] += a[i] * w[j];
        }
        __syncthreads();
    }

#pragma unroll
    for (int j = 0; j < 4; j++) {
        int n = col0 + tx * 4 + j;
        float bb = bias[n];
#pragma unroll
        for (int i = 0; i < 4; i++) {
            int m = row0 + ty * 4 + i;
            float v = acc[i * 4 + j] + bb;
            size_t oi = (size_t)m * ldc + n;
            if (ep_z != nullptr) {
                v = ep_z[oi] + ep_h6 * (ep_k1[oi] + 2.0f * (ep_k2[oi] + ep_k3[oi]) + v);
            } else if (act == 1) {
                v = tanhf(v);
            }
            C[oi] = v;
        }
    }
}

// ---------------- split z0_out -> (mean, logvar) outputs + ODE init node ----------------
__global__ void split_kernel(float* __restrict__ out_mean, float* __restrict__ out_logvar) {
    int i = blockIdx.x * blockDim.x + threadIdx.x;
    if (i >= BL_) return;
    int b = i >> 7, j = i & 127;
    float m  = g_z0out[(size_t)b * (2 * L_) + j];
    float lv = g_z0out[(size_t)b * (2 * L_) + L_ + j];
    out_mean[i] = m;
    out_logvar[i] = lv;
    g_znode[i] = m;           // znode[0] = z0
}

// ---------------- DeepHit head with fused Hermite dense output ----------------
__global__ __launch_bounds__(256) void head_kernel(
    const float* __restrict__ sh_w1, const float* __restrict__ sh_b1,
    const float* __restrict__ sh_w2, const float* __restrict__ sh_b2,
    float* __restrict__ hazard_out)
{
    __shared__ float w1s[32 * 129];
    __shared__ float b1s[32];
    __shared__ float w2s[32];
    __shared__ float b2s;
    __shared__ float zb[8][128];

    int tid = threadIdx.x;
#pragma unroll
    for (int i = 0; i < 16; i++) {
        int e = tid + i * 256;        // e = m*128 + k
        int m = e >> 7, k = e & 127;
        w1s[m * 129 + k] = sh_w1[e];
    }
    if (tid < 32) { b1s[tid] = sh_b1[tid]; w2s[tid] = sh_w2[tid]; }
    if (tid == 0) b2s = sh_b2[0];
    __syncthreads();

    int warp = tid >> 5, lane = tid & 31;
    int row = blockIdx.x * 8 + warp;               // over B_*NH_
    int b = row / NH_, j = row - b * NH_;

    float t = (float)j / (float)(NH_ - 1);
    float ts = t * (float)NS_;
    int iv = (int)ts; if (iv > NS_ - 1) iv = NS_ - 1;
    float th = ts - (float)iv;
    float th2 = th * th, th3 = th2 * th;
    float h00 = 2.f * th3 - 3.f * th2 + 1.f;
    float h10 = th3 - 2.f * th2 + th;
    float h01 = -2.f * th3 + 3.f * th2;
    float h11 = th3 - th2;
    float hstep = 1.0f / (float)NS_;

    const float* z0r = g_znode + (size_t)iv * BL_ + (size_t)b * L_;
    const float* z1r = z0r + BL_;
    const float* f0r = g_fnode + (size_t)iv * BL_ + (size_t)b * L_;
    const float* f1r = f0r + BL_;
#pragma unroll
    for (int k = lane; k < 128; k += 32) {
        zb[warp][k] = h00 * z0r[k] + h01 * z1r[k] + hstep * (h10 * f0r[k] + h11 * f1r[k]);
    }
    __syncwarp();

    float s = 0.f;
#pragma unroll 8
    for (int k = 0; k < 128; k++) s += zb[warp][k] * w1s[lane * 129 + k];
    float hm = fmaxf(s + b1s[lane], 0.f);
    float p = hm * w2s[lane];
#pragma unroll
    for (int o = 16; o; o >>= 1) p += __shfl_down_sync(0xffffffffu, p, o);
    if (lane == 0) hazard_out[row] = sigmoidf_(p + b2s);
}

// ---------------- survival cumprod + p_global ----------------
__global__ void surv_kernel(const float* __restrict__ hazard,
                            float* __restrict__ survival, float* __restrict__ pg) {
    int b = blockIdx.x * blockDim.x + threadIdx.x;
    if (b >= B_) return;
    float ls = 0.f, sv = 1.f;
#pragma unroll
    for (int i = 0; i < NH_; i++) {
        sv = expf(ls);
        survival[b * NH_ + i] = sv;
        ls += logf(1.0f - hazard[b * NH_ + i] + 1e-7f);
    }
    pg[b] = 1.0f - sv;
}

// ---------------- host side ----------------
struct OdeW {
    const float *w1, *b1, *w2, *b2, *w3, *b3, *tpw, *tpb;
    float *m1, *m2;
};

// f(zin + s*zin2, t) -> kout ; optional RK4-combine epilogue on layer 3
static void ode_eval(const float* zin, const float* zin2, float s, float t, float* kout,
                     const OdeW& o,
                     const float* ep_z = nullptr, const float* ep_k1 = nullptr,
                     const float* ep_k2 = nullptr, const float* ep_k3 = nullptr,
                     float ep_h6 = 0.f)
{
    gemm128_kernel<<<dim3(B_ / 128, HID_ / 64), 256>>>(zin, zin2, s, L_, o.w1, L_ + E_, o.b1,
        o.m1, HID_, B_, HID_, L_, 1, o.tpw, o.tpb, t);
    gemm128_kernel<<<dim3(B_ / 128, HID_ / 64), 256>>>(o.m1, nullptr, 0.f, HID_, o.w2, HID_, o.b2,
        o.m2, HID_, B_, HID_, HID_, 1, nullptr, nullptr, 0.f);
    gemm64_kernel<<<dim3(B_ / 64, L_ / 64), 256>>>(o.m2, HID_, o.w3, HID_, o.b3,
        kout, L_, B_, L_, HID_, 0,
        ep_z, ep_k1, ep_k2, ep_k3, ep_h6);
}

extern "C" void kernel_launch(void* const* d_in, const int* in_sizes, int n_in,
                              void* d_out, int out_size) {
    const float* X        = (const float*)d_in[0];
    const float* mask     = (const float*)d_in[1];
    const float* gru_w_ih = (const float*)d_in[2];
    const float* gru_w_hh = (const float*)d_in[3];
    const float* gru_b_ih = (const float*)d_in[4];
    const float* gru_b_hh = (const float*)d_in[5];
    const float* z0_w     = (const float*)d_in[6];
    const float* z0_b     = (const float*)d_in[7];
    const float* tproj_w  = (const float*)d_in[8];
    const float* tproj_b  = (const float*)d_in[9];
    const float* ode_w1   = (const float*)d_in[10];
    const float* ode_b1   = (const float*)d_in[11];
    const float* ode_w2   = (const float*)d_in[12];
    const float* ode_b2   = (const float*)d_in[13];
    const float* ode_w3   = (const float*)d_in[14];
    const float* ode_b3   = (const float*)d_in[15];
    const float* sh_w1    = (const float*)d_in[16];
    const float* sh_b1    = (const float*)d_in[17];
    const float* sh_w2    = (const float*)d_in[18];
    const float* sh_b2    = (const float*)d_in[19];

    float* out = (float*)d_out;
    // output layout: hazard[B,NH] | survival[B,NH] | z0_mean[B,L] | z0_logvar[B,L] | p_global[B]
    float* o_haz  = out;
    float* o_surv = out + (size_t)B_ * NH_;
    float* o_mean = out + (size_t)2 * B_ * NH_;
    float* o_lvar = o_mean + (size_t)BL_;
    float* o_pg   = o_lvar + (size_t)BL_;

    float *hA, *hB, *z0out, *k2, *k3, *m1, *m2, *znode, *fnode;
    cudaGetSymbolAddress((void**)&hA, g_hA);
    cudaGetSymbolAddress((void**)&hB, g_hB);
    cudaGetSymbolAddress((void**)&z0out, g_z0out);
    cudaGetSymbolAddress((void**)&k2, g_k2);
    cudaGetSymbolAddress((void**)&k3, g_k3);
    cudaGetSymbolAddress((void**)&m1, g_m1);
    cudaGetSymbolAddress((void**)&m2, g_m2);
    cudaGetSymbolAddress((void**)&znode, g_znode);
    cudaGetSymbolAddress((void**)&fnode, g_fnode);

    OdeW ow{ode_w1, ode_b1, ode_w2, ode_b2, ode_w3, ode_b3, tproj_w, tproj_b, m1, m2};

    // ---- GRU encoder (reversed time) ----
    cudaMemsetAsync(hA, 0, (size_t)B_ * H_ * sizeof(float), 0);
    obs_kernel<<<(B_ * T_ + 255) / 256, 256>>>(mask);
    gih_kernel<<<dim3((B_ * T_) / 128, G3_ / 64), 256>>>(X, mask, gru_w_ih, gru_b_ih);

    float* hin = hA;
    float* hout = hB;
    for (int t = T_ - 1; t >= 0; t--) {
        gru_step_kernel<<<dim3(B_ / 128, H_ / 64), 256>>>(gru_w_hh, gru_b_hh, hin, hout, t);
        float* tmp = hin; hin = hout; hout = tmp;
    }

    // ---- z0 head: [B,256]@[256,256]^T ----
    gemm128_kernel<<<dim3(B_ / 128, (2 * L_) / 64), 256>>>(hin, nullptr, 0.f, H_, z0_w, H_, z0_b,
        z0out, 2 * L_, B_, 2 * L_, H_, 0, nullptr, nullptr, 0.f);
    split_kernel<<<(BL_ + 255) / 256, 256>>>(o_mean, o_lvar);

    // ---- ODE: NS_ fixed RK4 steps; nodes (z_i, f_i) kept for Hermite dense output ----
    const float h = 1.0f / (float)NS_;
    for (int i = 0; i < NS_; i++) {
        float t0 = (float)i * h;
        float tm = t0 + 0.5f * h;
        float t1 = t0 + h;
        float* zi = znode + (size_t)i * BL_;
        float* fi = fnode + (size_t)i * BL_;       // k1 lives here
        float* zn = znode + (size_t)(i + 1) * BL_;

        ode_eval(zi, nullptr, 0.f, t0, fi, ow);                          // k1 = f(z_i, t0)
        ode_eval(zi, fi, 0.5f * h, tm, k2, ow);                          // k2
        ode_eval(zi, k2, 0.5f * h, tm, k3, ow);                          // k3
        ode_eval(zi, k3, h, t1, zn, ow, zi, fi, k2, k3, h / 6.0f);       // k4 + combine -> z_{i+1}
    }
    // f at the final node (needed by Hermite on the last interval)
    ode_eval(znode + (size_t)NS_ * BL_, nullptr, 0.f, 1.0f, fnode + (size_t)NS_ * BL_, ow);

    // ---- DeepHit head (with fused dense-output interpolation) + survival ----
    head_kernel<<<(B_ * NH_) / 8, 256>>>(sh_w1, sh_b1, sh_w2, sh_b2, o_haz);
    surv_kernel<<<(B_ + 255) / 256, 256>>>(o_haz, o_surv, o_pg);
}

// round 7
// speedup vs baseline: 2.7308x; 1.1656x over previous
#include <cuda_runtime.h>
#include <math.h>
#include <stdint.h>

#define B_   4096
#define T_   48
#define D_   32
#define H_   256
#define G3_  768          // 3*H
#define L_   128
#define HID_ 256
#define E_   8
#define NH_  48
#define NS_  12           // RK4 steps over [0,1]
#define BL_  (B_ * L_)
#define PI_F 3.14159265358979323846f

// ---------------- scratch (device globals; no allocation allowed) ----------------
__device__ float g_hA[B_ * H_];
__device__ float g_hB[B_ * H_];
__device__ float g_obs[T_ * B_];
__device__ float g_gih[(size_t)T_ * B_ * G3_];   // precomputed inp@W_ih^T + b_ih, [t][b][768]
__device__ float g_z0out[B_ * 2 * L_];
__device__ float g_k2[BL_];
__device__ float g_k3[BL_];
__device__ float g_m1[B_ * HID_];
__device__ float g_m2[B_ * HID_];
__device__ float g_znode[(NS_ + 1) * BL_];   // z at RK4 nodes
__device__ float g_fnode[(NS_ + 1) * BL_];   // f(z,t) at RK4 nodes

__device__ __forceinline__ float sigmoidf_(float x) {
    return 1.0f / (1.0f + expf(-x));
}

// ---------------- tf32 helpers ----------------
__device__ __forceinline__ uint32_t f2tf(float x) {
    uint32_t r;
    asm("cvt.rna.tf32.f32 %0, %1;" : "=r"(r) : "f"(x));
    return r;
}
__device__ __forceinline__ void split_tf(float x, uint32_t& hi, uint32_t& lo) {
    hi = f2tf(x);
    lo = f2tf(x - __uint_as_float(hi));
}
// D(16x8) += A(16x8) * B(8x8); documented m16n8k8 tf32 fragment layouts.
__device__ __forceinline__ void mma8(float* c, const uint32_t* a, uint32_t b0, uint32_t b1) {
    asm volatile(
        "mma.sync.aligned.m16n8k8.row.col.f32.tf32.tf32.f32 "
        "{%0,%1,%2,%3}, {%4,%5,%6,%7}, {%8,%9}, {%0,%1,%2,%3};"
        : "+f"(c[0]), "+f"(c[1]), "+f"(c[2]), "+f"(c[3])
        : "r"(a[0]), "r"(a[1]), "r"(a[2]), "r"(a[3]), "r"(b0), "r"(b1));
}

// ---------------- obs mask: any_obs[t,b] = (sum_k mask[b,t,k]) > 0 ----------------
__global__ void obs_kernel(const float* __restrict__ mask) {
    int i = blockIdx.x * blockDim.x + threadIdx.x;  // over B_*T_
    if (i >= B_ * T_) return;
    int b = i / T_, t = i % T_;
    const float* mp = mask + (size_t)i * D_;
    float s = 0.f;
#pragma unroll
    for (int k = 0; k < D_; k++) s += mp[k];
    g_obs[t * B_ + b] = (s > 0.f) ? 1.0f : 0.0f;
}

// ---------------- gih precompute (tensor): [X,mask] @ w_ih^T + b_ih -> [t][b][768] ----------------
__global__ __launch_bounds__(256) void gih_tc(
    const float* __restrict__ X, const float* __restrict__ mask,
    const float* __restrict__ w_ih, const float* __restrict__ b_ih)
{
    __shared__ float As[128][36];
    __shared__ float Ws[64][36];

    int tid = threadIdx.x;
    int wid = tid >> 5, lane = tid & 31, gid = lane >> 2, tig = lane & 3;
    int warp_m = wid & 3, warp_n = wid >> 2;
    int row0 = blockIdx.x * 128;   // over r = b*T + t
    int col0 = blockIdx.y * 64;    // over 768

    float acc[2][4][4];
#pragma unroll
    for (int mi = 0; mi < 2; mi++)
#pragma unroll
        for (int nj = 0; nj < 4; nj++)
#pragma unroll
            for (int e = 0; e < 4; e++) acc[mi][nj][e] = 0.f;

    for (int kc = 0; kc < 2; kc++) {
        const float* Ab = (kc == 0) ? X : mask;
        int k0 = kc * 32;
#pragma unroll
        for (int i = 0; i < 16; i++) {
            int e = tid + i * 256;
            int m = e >> 5, k = e & 31;
            As[m][k] = Ab[(size_t)(row0 + m) * D_ + k];
        }
#pragma unroll
        for (int i = 0; i < 8; i++) {
            int e = tid + i * 256;
            int n = e >> 5, k = e & 31;
            Ws[n][k] = w_ih[(size_t)(col0 + n) * 64 + k0 + k];
        }
        __syncthreads();
#pragma unroll
        for (int k8 = 0; k8 < 4; k8++) {
            int kb = k8 * 8;
            uint32_t ahi[2][4], alo[2][4];
#pragma unroll
            for (int mi = 0; mi < 2; mi++) {
                int rb = warp_m * 32 + mi * 16;
                split_tf(As[rb + gid][kb + tig],         ahi[mi][0], alo[mi][0]);
                split_tf(As[rb + gid + 8][kb + tig],     ahi[mi][1], alo[mi][1]);
                split_tf(As[rb + gid][kb + tig + 4],     ahi[mi][2], alo[mi][2]);
                split_tf(As[rb + gid + 8][kb + tig + 4], ahi[mi][3], alo[mi][3]);
            }
#pragma unroll
            for (int nj = 0; nj < 4; nj++) {
                int wr = warp_n * 32 + nj * 8 + gid;
                uint32_t bh0, bl0, bh1, bl1;
                split_tf(Ws[wr][kb + tig], bh0, bl0);
                split_tf(Ws[wr][kb + tig + 4], bh1, bl1);
#pragma unroll
                for (int mi = 0; mi < 2; mi++) {
                    mma8(acc[mi][nj], ahi[mi], bh0, bh1);
                    mma8(acc[mi][nj], alo[mi], bh0, bh1);
                    mma8(acc[mi][nj], ahi[mi], bl0, bl1);
                }
            }
        }
        __syncthreads();
    }

#pragma unroll
    for (int mi = 0; mi < 2; mi++)
#pragma unroll
        for (int e = 0; e < 4; e++) {
            int r = row0 + warp_m * 32 + mi * 16 + gid + (e >> 1) * 8;
            int b = r / T_, t = r - b * T_;
            size_t ob = ((size_t)t * B_ + b) * G3_;
#pragma unroll
            for (int nj = 0; nj < 4; nj++) {
                int n = col0 + warp_n * 32 + nj * 8 + tig * 2 + (e & 1);
                g_gih[ob + n] = acc[mi][nj][e] + b_ih[n];
            }
        }
}

// ---------------- GRU step (tensor): 3-gate h @ w_hh^T, fused gate epilogue ----------------
__global__ __launch_bounds__(256) void gru_step_tc(
    const float* __restrict__ w_hh, const float* __restrict__ b_hh,
    const float* __restrict__ h_in, float* __restrict__ h_out, int t)
{
    __shared__ float As[128][36];      // h tile
    __shared__ float Ws[192][36];      // 3 gates x 64 cols of w_hh
    __shared__ float bhh_s[192];

    int tid = threadIdx.x;
    int wid = tid >> 5, lane = tid & 31, gid = lane >> 2, tig = lane & 3;
    int warp_m = wid & 3, warp_n = wid >> 2;
    int row0 = blockIdx.x * 128;
    int col0 = blockIdx.y * 64;

    if (tid < 192) {
        int g = tid / 64, j = tid - g * 64;
        bhh_s[tid] = b_hh[g * 256 + col0 + j];
    }

    float acc[3][2][4][4];
#pragma unroll
    for (int g = 0; g < 3; g++)
#pragma unroll
        for (int mi = 0; mi < 2; mi++)
#pragma unroll
            for (int nj = 0; nj < 4; nj++)
#pragma unroll
                for (int e = 0; e < 4; e++) acc[g][mi][nj][e] = 0.f;

    for (int kc = 0; kc < 8; kc++) {
        int k0 = kc * 32;
#pragma unroll
        for (int i = 0; i < 16; i++) {
            int e = tid + i * 256;
            int m = e >> 5, k = e & 31;
            As[m][k] = h_in[(size_t)(row0 + m) * H_ + k0 + k];
        }
#pragma unroll
        for (int i = 0; i < 24; i++) {
            int e = tid + i * 256;
            int wr = e >> 5, k = e & 31;
            int g = wr >> 6, j = wr & 63;
            Ws[wr][k] = w_hh[(size_t)(g * 256 + col0 + j) * H_ + k0 + k];
        }
        __syncthreads();
#pragma unroll
        for (int k8 = 0; k8 < 4; k8++) {
            int kb = k8 * 8;
            uint32_t ahi[2][4], alo[2][4];
#pragma unroll
            for (int mi = 0; mi < 2; mi++) {
                int rb = warp_m * 32 + mi * 16;
                split_tf(As[rb + gid][kb + tig],         ahi[mi][0], alo[mi][0]);
                split_tf(As[rb + gid + 8][kb + tig],     ahi[mi][1], alo[mi][1]);
                split_tf(As[rb + gid][kb + tig + 4],     ahi[mi][2], alo[mi][2]);
                split_tf(As[rb + gid + 8][kb + tig + 4], ahi[mi][3], alo[mi][3]);
            }
#pragma unroll
            for (int g = 0; g < 3; g++)
#pragma unroll
                for (int nj = 0; nj < 4; nj++) {
                    int wr = g * 64 + warp_n * 32 + nj * 8 + gid;
                    uint32_t bh0, bl0, bh1, bl1;
                    split_tf(Ws[wr][kb + tig], bh0, bl0);
                    split_tf(Ws[wr][kb + tig + 4], bh1, bl1);
#pragma unroll
                    for (int mi = 0; mi < 2; mi++) {
                        mma8(acc[g][mi][nj], ahi[mi], bh0, bh1);
                        mma8(acc[g][mi][nj], alo[mi], bh0, bh1);
                        mma8(acc[g][mi][nj], ahi[mi], bl0, bl1);
                    }
                }
        }
        __syncthreads();
    }

    // ---- epilogue: gates + mask-gated state update (all in registers) ----
#pragma unroll
    for (int mi = 0; mi < 2; mi++)
#pragma unroll
        for (int e = 0; e < 4; e++) {
            int row = row0 + warp_m * 32 + mi * 16 + gid + (e >> 1) * 8;
            float o = g_obs[t * B_ + row];
            const float* gih = &g_gih[((size_t)t * B_ + row) * G3_];
#pragma unroll
            for (int nj = 0; nj < 4; nj++) {
                int jl = warp_n * 32 + nj * 8 + tig * 2 + (e & 1);
                int j = col0 + jl;
                float r  = sigmoidf_(acc[0][mi][nj][e] + gih[j] + bhh_s[jl]);
                float zg = sigmoidf_(acc[1][mi][nj][e] + gih[256 + j] + bhh_s[64 + jl]);
                float nn = tanhf(gih[512 + j] + r * (acc[2][mi][nj][e] + bhh_s[128 + jl]));
                float hp = h_in[(size_t)row * H_ + j];
                float hn = (1.0f - zg) * nn + zg * hp;
                h_out[(size_t)row * H_ + j] = o * hn + (1.0f - o) * hp;
            }
        }
}

// ---------------- generic tensor GEMM 128x64: C = act((A + s*A2) @ W^T + b [+temb] ) ----------------
// Optional RK4-combine epilogue: C = ep_z + ep_h6*(ep_k1 + 2*ep_k2 + 2*ep_k3 + (acc+b))
__global__ __launch_bounds__(256) void gemm_tc(
    const float* __restrict__ A, const float* __restrict__ A2, float ascale, int lda,
    const float* __restrict__ W, int ldw,
    const float* __restrict__ bias,
    float* __restrict__ C, int ldc,
    int K, int act,
    const float* __restrict__ tproj_w, const float* __restrict__ tproj_b, float tval,
    const float* __restrict__ ep_z, const float* __restrict__ ep_k1,
    const float* __restrict__ ep_k2, const float* __restrict__ ep_k3, float ep_h6)
{
    __shared__ float As[128][36];
    __shared__ float Ws[64][36];
    __shared__ float temb[8];

    int tid = threadIdx.x;
    int wid = tid >> 5, lane = tid & 31, gid = lane >> 2, tig = lane & 3;
    int warp_m = wid & 3, warp_n = wid >> 2;
    int row0 = blockIdx.x * 128;
    int col0 = blockIdx.y * 64;

    if (tproj_w != nullptr && tid < 8) {
        float s = 0.f;
#pragma unroll
        for (int f = 0; f < 8; f++) {
            float arg = (f < 4) ? (tval * (float)(f + 1) * PI_F) : (tval * (float)(f - 3) * PI_F);
            float em = (f < 4) ? sinf(arg) : cosf(arg);
            s += tproj_w[tid * 8 + f] * em;
        }
        temb[tid] = s + tproj_b[tid];
    }

    float acc[2][4][4];
#pragma unroll
    for (int mi = 0; mi < 2; mi++)
#pragma unroll
        for (int nj = 0; nj < 4; nj++)
#pragma unroll
            for (int e = 0; e < 4; e++) acc[mi][nj][e] = 0.f;

    for (int k0 = 0; k0 < K; k0 += 32) {
#pragma unroll
        for (int i = 0; i < 16; i++) {
            int e = tid + i * 256;
            int m = e >> 5, k = e & 31;
            size_t gi = (size_t)(row0 + m) * lda + k0 + k;
            float v = A[gi];
            if (A2 != nullptr) v += ascale * A2[gi];
            As[m][k] = v;
        }
#pragma unroll
        for (int i = 0; i < 8; i++) {
            int e = tid + i * 256;
            int n = e >> 5, k = e & 31;
            Ws[n][k] = W[(size_t)(col0 + n) * ldw + k0 + k];
        }
        __syncthreads();
#pragma unroll
        for (int k8 = 0; k8 < 4; k8++) {
            int kb = k8 * 8;
            uint32_t ahi[2][4], alo[2][4];
#pragma unroll
            for (int mi = 0; mi < 2; mi++) {
                int rb = warp_m * 32 + mi * 16;
                split_tf(As[rb + gid][kb + tig],         ahi[mi][0], alo[mi][0]);
                split_tf(As[rb + gid + 8][kb + tig],     ahi[mi][1], alo[mi][1]);
                split_tf(As[rb + gid][kb + tig + 4],     ahi[mi][2], alo[mi][2]);
                split_tf(As[rb + gid + 8][kb + tig + 4], ahi[mi][3], alo[mi][3]);
            }
#pragma unroll
            for (int nj = 0; nj < 4; nj++) {
                int wr = warp_n * 32 + nj * 8 + gid;
                uint32_t bh0, bl0, bh1, bl1;
                split_tf(Ws[wr][kb + tig], bh0, bl0);
                split_tf(Ws[wr][kb + tig + 4], bh1, bl1);
#pragma unroll
                for (int mi = 0; mi < 2; mi++) {
                    mma8(acc[mi][nj], ahi[mi], bh0, bh1);
                    mma8(acc[mi][nj], alo[mi], bh0, bh1);
                    mma8(acc[mi][nj], ahi[mi], bl0, bl1);
                }
            }
        }
        __syncthreads();
    }

#pragma unroll
    for (int nj = 0; nj < 4; nj++) {
#pragma unroll
        for (int e01 = 0; e01 < 2; e01++) {
            int n = col0 + warp_n * 32 + nj * 8 + tig * 2 + e01;
            float tadd = 0.f;
            if (tproj_w != nullptr) {
#pragma unroll
                for (int f = 0; f < 8; f++) tadd += temb[f] * W[(size_t)n * ldw + K + f];
            }
            float bb = bias[n] + tadd;
#pragma unroll
            for (int mi = 0; mi < 2; mi++)
#pragma unroll
                for (int eh = 0; eh < 2; eh++) {
                    int m = row0 + warp_m * 32 + mi * 16 + gid + eh * 8;
                    float v = acc[mi][nj][eh * 2 + e01] + bb;
                    size_t oi = (size_t)m * ldc + n;
                    if (ep_z != nullptr) {
                        v = ep_z[oi] + ep_h6 * (ep_k1[oi] + 2.0f * (ep_k2[oi] + ep_k3[oi]) + v);
                    } else if (act == 1) {
                        v = tanhf(v);
                    }
                    C[oi] = v;
                }
        }
    }
}

// ---------------- split z0_out -> (mean, logvar) outputs + ODE init node ----------------
__global__ void split_kernel(float* __restrict__ out_mean, float* __restrict__ out_logvar) {
    int i = blockIdx.x * blockDim.x + threadIdx.x;
    if (i >= BL_) return;
    int b = i >> 7, j = i & 127;
    float m  = g_z0out[(size_t)b * (2 * L_) + j];
    float lv = g_z0out[(size_t)b * (2 * L_) + L_ + j];
    out_mean[i] = m;
    out_logvar[i] = lv;
    g_znode[i] = m;           // znode[0] = z0
}

// ---------------- DeepHit head with fused Hermite dense output ----------------
__global__ __launch_bounds__(256) void head_kernel(
    const float* __restrict__ sh_w1, const float* __restrict__ sh_b1,
    const float* __restrict__ sh_w2, const float* __restrict__ sh_b2,
    float* __restrict__ hazard_out)
{
    __shared__ float w1s[32 * 129];
    __shared__ float b1s[32];
    __shared__ float w2s[32];
    __shared__ float b2s;
    __shared__ float zb[8][128];

    int tid = threadIdx.x;
#pragma unroll
    for (int i = 0; i < 16; i++) {
        int e = tid + i * 256;        // e = m*128 + k
        int m = e >> 7, k = e & 127;
        w1s[m * 129 + k] = sh_w1[e];
    }
    if (tid < 32) { b1s[tid] = sh_b1[tid]; w2s[tid] = sh_w2[tid]; }
    if (tid == 0) b2s = sh_b2[0];
    __syncthreads();

    int warp = tid >> 5, lane = tid & 31;
    int row = blockIdx.x * 8 + warp;               // over B_*NH_
    int b = row / NH_, j = row - b * NH_;

    float t = (float)j / (float)(NH_ - 1);
    float ts = t * (float)NS_;
    int iv = (int)ts; if (iv > NS_ - 1) iv = NS_ - 1;
    float th = ts - (float)iv;
    float th2 = th * th, th3 = th2 * th;
    float h00 = 2.f * th3 - 3.f * th2 + 1.f;
    float h10 = th3 - 2.f * th2 + th;
    float h01 = -2.f * th3 + 3.f * th2;
    float h11 = th3 - th2;
    float hstep = 1.0f / (float)NS_;

    const float* z0r = g_znode + (size_t)iv * BL_ + (size_t)b * L_;
    const float* z1r = z0r + BL_;
    const float* f0r = g_fnode + (size_t)iv * BL_ + (size_t)b * L_;
    const float* f1r = f0r + BL_;
#pragma unroll
    for (int k = lane; k < 128; k += 32) {
        zb[warp][k] = h00 * z0r[k] + h01 * z1r[k] + hstep * (h10 * f0r[k] + h11 * f1r[k]);
    }
    __syncwarp();

    float s = 0.f;
#pragma unroll 8
    for (int k = 0; k < 128; k++) s += zb[warp][k] * w1s[lane * 129 + k];
    float hm = fmaxf(s + b1s[lane], 0.f);
    float p = hm * w2s[lane];
#pragma unroll
    for (int o = 16; o; o >>= 1) p += __shfl_down_sync(0xffffffffu, p, o);
    if (lane == 0) hazard_out[row] = sigmoidf_(p + b2s);
}

// ---------------- survival cumprod + p_global ----------------
__global__ void surv_kernel(const float* __restrict__ hazard,
                            float* __restrict__ survival, float* __restrict__ pg) {
    int b = blockIdx.x * blockDim.x + threadIdx.x;
    if (b >= B_) return;
    float ls = 0.f, sv = 1.f;
#pragma unroll
    for (int i = 0; i < NH_; i++) {
        sv = expf(ls);
        survival[b * NH_ + i] = sv;
        ls += logf(1.0f - hazard[b * NH_ + i] + 1e-7f);
    }
    pg[b] = 1.0f - sv;
}

// ---------------- host side ----------------
struct OdeW {
    const float *w1, *b1, *w2, *b2, *w3, *b3, *tpw, *tpb;
    float *m1, *m2;
};

// f(zin + s*zin2, t) -> kout ; optional RK4-combine epilogue on layer 3
static void ode_eval(const float* zin, const float* zin2, float s, float t, float* kout,
                     const OdeW& o,
                     const float* ep_z = nullptr, const float* ep_k1 = nullptr,
                     const float* ep_k2 = nullptr, const float* ep_k3 = nullptr,
                     float ep_h6 = 0.f)
{
    gemm_tc<<<dim3(B_ / 128, HID_ / 64), 256>>>(zin, zin2, s, L_, o.w1, L_ + E_, o.b1,
        o.m1, HID_, L_, 1, o.tpw, o.tpb, t,
        nullptr, nullptr, nullptr, nullptr, 0.f);
    gemm_tc<<<dim3(B_ / 128, HID_ / 64), 256>>>(o.m1, nullptr, 0.f, HID_, o.w2, HID_, o.b2,
        o.m2, HID_, HID_, 1, nullptr, nullptr, 0.f,
        nullptr, nullptr, nullptr, nullptr, 0.f);
    gemm_tc<<<dim3(B_ / 128, L_ / 64), 256>>>(o.m2, nullptr, 0.f, HID_, o.w3, HID_, o.b3,
        kout, L_, HID_, 0, nullptr, nullptr, 0.f,
        ep_z, ep_k1, ep_k2, ep_k3, ep_h6);
}

extern "C" void kernel_launch(void* const* d_in, const int* in_sizes, int n_in,
                              void* d_out, int out_size) {
    const float* X        = (const float*)d_in[0];
    const float* mask     = (const float*)d_in[1];
    const float* gru_w_ih = (const float*)d_in[2];
    const float* gru_w_hh = (const float*)d_in[3];
    const float* gru_b_ih = (const float*)d_in[4];
    const float* gru_b_hh = (const float*)d_in[5];
    const float* z0_w     = (const float*)d_in[6];
    const float* z0_b     = (const float*)d_in[7];
    const float* tproj_w  = (const float*)d_in[8];
    const float* tproj_b  = (const float*)d_in[9];
    const float* ode_w1   = (const float*)d_in[10];
    const float* ode_b1   = (const float*)d_in[11];
    const float* ode_w2   = (const float*)d_in[12];
    const float* ode_b2   = (const float*)d_in[13];
    const float* ode_w3   = (const float*)d_in[14];
    const float* ode_b3   = (const float*)d_in[15];
    const float* sh_w1    = (const float*)d_in[16];
    const float* sh_b1    = (const float*)d_in[17];
    const float* sh_w2    = (const float*)d_in[18];
    const float* sh_b2    = (const float*)d_in[19];

    float* out = (float*)d_out;
    // output layout: hazard[B,NH] | survival[B,NH] | z0_mean[B,L] | z0_logvar[B,L] | p_global[B]
    float* o_haz  = out;
    float* o_surv = out + (size_t)B_ * NH_;
    float* o_mean = out + (size_t)2 * B_ * NH_;
    float* o_lvar = o_mean + (size_t)BL_;
    float* o_pg   = o_lvar + (size_t)BL_;

    float *hA, *hB, *z0out, *k2, *k3, *m1, *m2, *znode, *fnode;
    cudaGetSymbolAddress((void**)&hA, g_hA);
    cudaGetSymbolAddress((void**)&hB, g_hB);
    cudaGetSymbolAddress((void**)&z0out, g_z0out);
    cudaGetSymbolAddress((void**)&k2, g_k2);
    cudaGetSymbolAddress((void**)&k3, g_k3);
    cudaGetSymbolAddress((void**)&m1, g_m1);
    cudaGetSymbolAddress((void**)&m2, g_m2);
    cudaGetSymbolAddress((void**)&znode, g_znode);
    cudaGetSymbolAddress((void**)&fnode, g_fnode);

    OdeW ow{ode_w1, ode_b1, ode_w2, ode_b2, ode_w3, ode_b3, tproj_w, tproj_b, m1, m2};

    // ---- GRU encoder (reversed time) ----
    cudaMemsetAsync(hA, 0, (size_t)B_ * H_ * sizeof(float), 0);
    obs_kernel<<<(B_ * T_ + 255) / 256, 256>>>(mask);
    gih_tc<<<dim3((B_ * T_) / 128, G3_ / 64), 256>>>(X, mask, gru_w_ih, gru_b_ih);

    float* hin = hA;
    float* hout = hB;
    for (int t = T_ - 1; t >= 0; t--) {
        gru_step_tc<<<dim3(B_ / 128, H_ / 64), 256>>>(gru_w_hh, gru_b_hh, hin, hout, t);
        float* tmp = hin; hin = hout; hout = tmp;
    }

    // ---- z0 head: [B,256]@[256,256]^T ----
    gemm_tc<<<dim3(B_ / 128, (2 * L_) / 64), 256>>>(hin, nullptr, 0.f, H_, z0_w, H_, z0_b,
        z0out, 2 * L_, H_, 0, nullptr, nullptr, 0.f,
        nullptr, nullptr, nullptr, nullptr, 0.f);
    split_kernel<<<(BL_ + 255) / 256, 256>>>(o_mean, o_lvar);

    // ---- ODE: NS_ fixed RK4 steps; nodes (z_i, f_i) kept for Hermite dense output ----
    const float h = 1.0f / (float)NS_;
    for (int i = 0; i < NS_; i++) {
        float t0 = (float)i * h;
        float tm = t0 + 0.5f * h;
        float t1 = t0 + h;
        float* zi = znode + (size_t)i * BL_;
        float* fi = fnode + (size_t)i * BL_;       // k1 lives here
        float* zn = znode + (size_t)(i + 1) * BL_;

        ode_eval(zi, nullptr, 0.f, t0, fi, ow);                          // k1 = f(z_i, t0)
        ode_eval(zi, fi, 0.5f * h, tm, k2, ow);                          // k2
        ode_eval(zi, k2, 0.5f * h, tm, k3, ow);                          // k3
        ode_eval(zi, k3, h, t1, zn, ow, zi, fi, k2, k3, h / 6.0f);       // k4 + combine -> z_{i+1}
    }
    // f at the final node (needed by Hermite on the last interval)
    ode_eval(znode + (size_t)NS_ * BL_, nullptr, 0.f, 1.0f, fnode + (size_t)NS_ * BL_, ow);

    // ---- DeepHit head (with fused dense-output interpolation) + survival ----
    head_kernel<<<(B_ * NH_) / 8, 256>>>(sh_w1, sh_b1, sh_w2, sh_b2, o_haz);
    surv_kernel<<<(B_ + 255) / 256, 256>>>(o_haz, o_surv, o_pg);
}